// round 2
// baseline (speedup 1.0000x reference)
#include <cuda_runtime.h>
#include <cuda_fp16.h>
#include <math.h>

#define EMB   1024
#define HID   2048
#define VOCAB 50257
#define T     256
#define NBLK  ((VOCAB + 7) / 8)     // 6283 pass1 blocks
#define NKEY  (2 * NBLK)            // per-block top-2 keys
#define NCAND 8                     // exact-recompute candidates

// Persistent device state (allocation-free scratch).
__device__ float g_h[2][HID];
__device__ float g_c[HID];
__device__ unsigned long long g_amax[T];        // exact packed argmax per step
__device__ unsigned long long g_blockbest[NKEY];
__device__ __half g_Wout_h[VOCAB * HID];        // fp16 copy of W_out (~206MB)

__device__ __forceinline__ unsigned long long pack_key(float v, int row) {
    unsigned ub = __float_as_uint(v);
    ub = (ub & 0x80000000u) ? ~ub : (ub | 0x80000000u);   // orderable float
    return ((unsigned long long)ub << 32) |
           (unsigned long long)(0xFFFFFFFFu - (unsigned)row);  // first-index ties
}

// ---------------------------------------------------------------------------
// W_out fp32 -> fp16 conversion (runs once per graph replay, ~90us).
// ---------------------------------------------------------------------------
__global__ void convert_wout(const float* __restrict__ W) {
    size_t n = (size_t)VOCAB * HID / 8;
    size_t stride = (size_t)gridDim.x * blockDim.x;
    for (size_t i = (size_t)blockIdx.x * blockDim.x + threadIdx.x; i < n; i += stride) {
        const float4* p = (const float4*)W + 2 * i;
        float4 a = p[0], b = p[1];
        __half2* o = (__half2*)g_Wout_h + 4 * i;
        o[0] = __floats2half2_rn(a.x, a.y);
        o[1] = __floats2half2_rn(a.z, a.w);
        o[2] = __floats2half2_rn(b.x, b.y);
        o[3] = __floats2half2_rn(b.z, b.w);
    }
}

__global__ void init_kernel() {
    int i = blockIdx.x * blockDim.x + threadIdx.x;
    if (i < HID) {
        g_h[0][i] = 0.0f;
        g_h[1][i] = 0.0f;
        g_c[i]    = 0.0f;
    }
    if (i < T) g_amax[i] = 0ULL;
}

// ---------------------------------------------------------------------------
// LSTM step (full fp32): warp-per-(gate,j). 1024 blocks x 256 thr = 8192 warps
// (vs 2048 before) -> ~1 dense wave on 152 SMs, much better DRAM utilization.
// ---------------------------------------------------------------------------
__global__ void __launch_bounds__(256) lstm_step_kernel(
    const float* __restrict__ emb,
    const float* __restrict__ W_ih,
    const float* __restrict__ W_hh,
    const float* __restrict__ b_ih,
    const float* __restrict__ b_hh,
    int step)
{
    __shared__ float sx[EMB];
    __shared__ float sh[HID];
    __shared__ float sg[2][4];

    int tok = 0;
    if (step > 0)
        tok = (int)(0xFFFFFFFFu - (unsigned)(g_amax[step - 1] & 0xFFFFFFFFull));

    const float* __restrict__ hprev = g_h[step & 1];
    float* __restrict__ hnext       = g_h[(step + 1) & 1];

    const float* __restrict__ xrow = emb + (size_t)tok * EMB;
    for (int i = threadIdx.x; i < EMB; i += 256) sx[i] = xrow[i];
    for (int i = threadIdx.x; i < HID; i += 256) sh[i] = hprev[i];
    __syncthreads();

    const int wid  = threadIdx.x >> 5;
    const int lane = threadIdx.x & 31;
    const int jl   = wid >> 2;          // 0..1
    const int gate = wid & 3;           // i,f,g,o
    const int j    = blockIdx.x * 2 + jl;
    const int row  = gate * HID + j;

    float a = 0.f;
    const float4* __restrict__ w1  = (const float4*)(W_ih + (size_t)row * EMB);
    const float4* __restrict__ s4x = (const float4*)sx;
    #pragma unroll
    for (int k = 0; k < EMB / 128; k++) {
        float4 w = w1[lane + 32 * k];
        float4 v = s4x[lane + 32 * k];
        a += w.x * v.x + w.y * v.y + w.z * v.z + w.w * v.w;
    }
    const float4* __restrict__ w2  = (const float4*)(W_hh + (size_t)row * HID);
    const float4* __restrict__ s4h = (const float4*)sh;
    #pragma unroll
    for (int k = 0; k < HID / 128; k++) {
        float4 w = w2[lane + 32 * k];
        float4 v = s4h[lane + 32 * k];
        a += w.x * v.x + w.y * v.y + w.z * v.z + w.w * v.w;
    }

    #pragma unroll
    for (int off = 16; off; off >>= 1)
        a += __shfl_down_sync(0xFFFFFFFFu, a, off);

    if (lane == 0) sg[jl][gate] = a;
    __syncthreads();

    if (threadIdx.x < 2) {
        const int jj = blockIdx.x * 2 + threadIdx.x;
        float ipre = sg[threadIdx.x][0] + b_ih[jj]           + b_hh[jj];
        float fpre = sg[threadIdx.x][1] + b_ih[HID + jj]     + b_hh[HID + jj];
        float gpre = sg[threadIdx.x][2] + b_ih[2 * HID + jj] + b_hh[2 * HID + jj];
        float opre = sg[threadIdx.x][3] + b_ih[3 * HID + jj] + b_hh[3 * HID + jj];

        float ig = 1.0f / (1.0f + expf(-ipre));
        float fg = 1.0f / (1.0f + expf(-fpre));
        float gg = tanhf(gpre);
        float og = 1.0f / (1.0f + expf(-opre));

        float c = fg * g_c[jj] + ig * gg;
        g_c[jj]   = c;
        hnext[jj] = og * tanhf(c);
    }
}

// ---------------------------------------------------------------------------
// Logits pass 1: fp16 weights (half the DRAM traffic). Warp-per-row.
// Writes approximate logits + per-block top-2 packed keys (no atomics).
// ---------------------------------------------------------------------------
__global__ void __launch_bounds__(256) logits_pass1(
    const float* __restrict__ b_out,
    float* __restrict__ out,
    int step)
{
    __shared__ __half2 sh2[HID / 2];
    __shared__ unsigned long long skey[8];

    const float2* __restrict__ h2 = (const float2*)g_h[(step + 1) & 1];
    for (int i = threadIdx.x; i < HID / 2; i += 256) {
        float2 v = h2[i];
        sh2[i] = __floats2half2_rn(v.x, v.y);
    }
    __syncthreads();

    const int wid  = threadIdx.x >> 5;
    const int lane = threadIdx.x & 31;
    const int row  = blockIdx.x * 8 + wid;

    unsigned long long key = 0ULL;
    if (row < VOCAB) {
        const int4* __restrict__ wp = (const int4*)(g_Wout_h + (size_t)row * HID);
        const int4* __restrict__ hp = (const int4*)sh2;

        float a = 0.f;
        #pragma unroll
        for (int k = 0; k < HID / 256; k++) {       // 8 iters of 8 halves
            int4 w = wp[lane + 32 * k];
            int4 h = hp[lane + 32 * k];
            float2 wf, hf;
            wf = __half22float2(*(__half2*)&w.x); hf = __half22float2(*(__half2*)&h.x);
            a += wf.x * hf.x + wf.y * hf.y;
            wf = __half22float2(*(__half2*)&w.y); hf = __half22float2(*(__half2*)&h.y);
            a += wf.x * hf.x + wf.y * hf.y;
            wf = __half22float2(*(__half2*)&w.z); hf = __half22float2(*(__half2*)&h.z);
            a += wf.x * hf.x + wf.y * hf.y;
            wf = __half22float2(*(__half2*)&w.w); hf = __half22float2(*(__half2*)&h.w);
            a += wf.x * hf.x + wf.y * hf.y;
        }

        #pragma unroll
        for (int off = 16; off; off >>= 1)
            a += __shfl_down_sync(0xFFFFFFFFu, a, off);

        if (lane == 0) {
            float logit = a + b_out[row];
            out[(size_t)step * VOCAB + row] = logit;
            key = pack_key(logit, row);
        }
    }
    if (lane == 0) skey[wid] = key;
    __syncthreads();

    if (threadIdx.x == 0) {
        unsigned long long b1 = 0ULL, b2 = 0ULL;
        #pragma unroll
        for (int i = 0; i < 8; i++) {
            unsigned long long k = skey[i];
            if (k > b1) { b2 = b1; b1 = k; }
            else if (k > b2) b2 = k;
        }
        g_blockbest[2 * blockIdx.x]     = b1;
        g_blockbest[2 * blockIdx.x + 1] = b2;
    }
}

// ---------------------------------------------------------------------------
// Logits pass 2 (1 block, 1024 thr): select top-NCAND approx keys from the
// per-block top-2 pool, recompute those rows exactly in fp32, pick the exact
// argmax (first-index ties) -> token path identical to full-fp32.
// ---------------------------------------------------------------------------
__global__ void __launch_bounds__(1024) logits_pass2(
    const float* __restrict__ W_out,
    const float* __restrict__ b_out,
    float* __restrict__ out,
    int step)
{
    extern __shared__ unsigned long long sk[];      // NKEY + 1024 + NCAND
    unsigned long long* red  = sk + NKEY;
    unsigned long long* cand = red + 1024;
    const int tid = threadIdx.x;

    for (int i = tid; i < NKEY; i += 1024) sk[i] = g_blockbest[i];
    __syncthreads();

    for (int r = 0; r < NCAND; r++) {
        unsigned long long m = 0ULL;
        for (int i = tid; i < NKEY; i += 1024) { unsigned long long k = sk[i]; if (k > m) m = k; }
        red[tid] = m;
        __syncthreads();
        for (int s = 512; s; s >>= 1) {
            if (tid < s) { if (red[tid + s] > red[tid]) red[tid] = red[tid + s]; }
            __syncthreads();
        }
        unsigned long long best = red[0];
        if (tid == 0) cand[r] = best;
        for (int i = tid; i < NKEY; i += 1024) if (sk[i] == best) sk[i] = 0ULL;
        __syncthreads();
    }

    const int wid  = tid >> 5;
    const int lane = tid & 31;
    if (wid < NCAND) {
        unsigned long long k = cand[wid];
        if (k != 0ULL) {
            const int row = (int)(0xFFFFFFFFu - (unsigned)(k & 0xFFFFFFFFull));
            const float4* __restrict__ wp = (const float4*)(W_out + (size_t)row * HID);
            const float4* __restrict__ hp = (const float4*)g_h[(step + 1) & 1];
            float a = 0.f;
            #pragma unroll
            for (int kk = 0; kk < HID / 128; kk++) {
                float4 w = wp[lane + 32 * kk];
                float4 v = hp[lane + 32 * kk];
                a += w.x * v.x + w.y * v.y + w.z * v.z + w.w * v.w;
            }
            #pragma unroll
            for (int off = 16; off; off >>= 1)
                a += __shfl_down_sync(0xFFFFFFFFu, a, off);
            if (lane == 0) {
                float logit = a + b_out[row];
                out[(size_t)step * VOCAB + row] = logit;   // exact overwrite
                cand[wid] = pack_key(logit, row);          // exact key
            }
        }
    }
    __syncthreads();

    if (tid == 0) {
        unsigned long long b = 0ULL;
        #pragma unroll
        for (int i = 0; i < NCAND; i++) if (cand[i] > b) b = cand[i];
        g_amax[step] = b;
    }
}

// ---------------------------------------------------------------------------
extern "C" void kernel_launch(void* const* d_in, const int* in_sizes, int n_in,
                              void* d_out, int out_size) {
    const float* emb   = (const float*)d_in[0];
    const float* W_ih  = (const float*)d_in[1];
    const float* W_hh  = (const float*)d_in[2];
    const float* b_ih  = (const float*)d_in[3];
    const float* b_hh  = (const float*)d_in[4];
    const float* W_out = (const float*)d_in[5];
    const float* b_out = (const float*)d_in[6];
    float* out = (float*)d_out;

    const int smem2 = (NKEY + 1024 + NCAND) * (int)sizeof(unsigned long long);
    cudaFuncSetAttribute(logits_pass2, cudaFuncAttributeMaxDynamicSharedMemorySize, smem2);

    convert_wout<<<2048, 256>>>(W_out);
    init_kernel<<<(HID + 255) / 256, 256>>>();

    for (int t = 0; t < T; t++) {
        lstm_step_kernel<<<HID / 2, 256>>>(emb, W_ih, W_hh, b_ih, b_hh, t);
        logits_pass1<<<NBLK, 256>>>(b_out, out, t);
        logits_pass2<<<1, 1024, smem2>>>(W_out, b_out, out, t);
    }
}